// round 2
// baseline (speedup 1.0000x reference)
#include <cuda_runtime.h>
#include <math.h>

// Problem constants
#define NN 17      // nodes
#define DD 512     // feature dim
#define HH 8       // heads
#define MM 256     // hidden dim of MLP
#define CIN 515    // D + 3

// ---------------- device scratch (no cudaMalloc allowed) ----------------
__device__ float g_pA[8][HH][NN][DD];   // partials of Xs@FC over 8 d-chunks
__device__ float g_f[HH][NN][DD];       // f = relu(Xs@FC)
__device__ float g_pB[8][HH][NN][MM];   // partials of cat@W1 over 8 c-chunks
__device__ float g_att[HH][NN][NN];     // softmaxed attention [h][k][n]

// ---------------- Kernel A: partial f = Xs @ FC ----------------
// grid: (dc=8, ec=4, h=8), block 128 (one e each)
__global__ void kA(const float* __restrict__ Xs, const float* __restrict__ FC) {
    const int dc = blockIdx.x;
    const int ec = blockIdx.y;
    const int h  = blockIdx.z;
    const int e  = ec * 128 + threadIdx.x;
    const int d0 = dc * 64;

    __shared__ float xs[NN][64];
    for (int idx = threadIdx.x; idx < NN * 64; idx += 128) {
        int n = idx >> 6, dd = idx & 63;
        xs[n][dd] = Xs[n * DD + d0 + dd];
    }
    __syncthreads();

    float acc[NN];
#pragma unroll
    for (int n = 0; n < NN; ++n) acc[n] = 0.f;

    const float* fcp = FC + ((size_t)h * DD + d0) * DD + e;
#pragma unroll 4
    for (int dd = 0; dd < 64; ++dd) {
        float fc = fcp[(size_t)dd * DD];
#pragma unroll
        for (int n = 0; n < NN; ++n)
            acc[n] = fmaf(xs[n][dd], fc, acc[n]);
    }
#pragma unroll
    for (int n = 0; n < NN; ++n)
        g_pA[dc][h][n][e] = acc[n];
}

// ---------------- Kernel B: reduce f chunk + relu, partial cat @ W1 ----------------
// grid: (cc=8, mc=2, h=8), block 128 (one m each)
__global__ void kB(const float* __restrict__ ROIs, const float* __restrict__ W1) {
    const int cc = blockIdx.x;
    const int mc = blockIdx.y;
    const int h  = blockIdx.z;
    const int m  = mc * 128 + threadIdx.x;
    const int c0 = cc * 64;

    __shared__ float cat_s[NN][64];
    __shared__ float coord_s[NN][3];

    for (int idx = threadIdx.x; idx < NN * 64; idx += 128) {
        int n = idx >> 6, cp = idx & 63;
        float v = 0.f;
#pragma unroll
        for (int dc = 0; dc < 8; ++dc) v += g_pA[dc][h][n][c0 + cp];
        v = fmaxf(v, 0.f);
        cat_s[n][cp] = v;
        if (mc == 0) g_f[h][n][c0 + cp] = v;
    }
    if (cc == 0) {
        for (int idx = threadIdx.x; idx < NN * 3; idx += 128)
            coord_s[idx / 3][idx % 3] = ROIs[idx];
    }
    __syncthreads();

    float acc[NN];
#pragma unroll
    for (int n = 0; n < NN; ++n) acc[n] = 0.f;

    const float* w1p = W1 + ((size_t)h * CIN + c0) * MM + m;
#pragma unroll 2
    for (int cp = 0; cp < 64; ++cp) {
        float w = w1p[(size_t)cp * MM];
#pragma unroll
        for (int n = 0; n < NN; ++n)
            acc[n] = fmaf(cat_s[n][cp], w, acc[n]);
    }
    if (cc == 0) {
#pragma unroll
        for (int j = 0; j < 3; ++j) {
            float w = W1[((size_t)h * CIN + DD + j) * MM + m];
#pragma unroll
            for (int n = 0; n < NN; ++n)
                acc[n] = fmaf(coord_s[n][j], w, acc[n]);
        }
    }
#pragma unroll
    for (int n = 0; n < NN; ++n)
        g_pB[cc][h][n][m] = acc[n];
}

// ---------------- Kernel C: reduce + bias + tanh, att = hdn@W2 + b2, softmax ----------------
// grid: 8 (one head per block), block 320
__global__ void kC(const float* __restrict__ W2, const float* __restrict__ b1,
                   const float* __restrict__ b2) {
    const int h = blockIdx.x;
    __shared__ float hdn[NN][MM];
    __shared__ float att[NN][NN];   // [k][n]

    for (int idx = threadIdx.x; idx < NN * MM; idx += 320) {
        int n = idx >> 8, m = idx & 255;
        float v = b1[h * MM + m];
#pragma unroll
        for (int cc = 0; cc < 8; ++cc) v += g_pB[cc][h][n][m];
        hdn[n][m] = tanhf(v);
    }
    __syncthreads();

    if (threadIdx.x < NN * NN) {
        int n = threadIdx.x / NN, k = threadIdx.x % NN;
        float s = b2[h * NN + k];
        const float* w2p = W2 + (size_t)h * MM * NN + k;
#pragma unroll 4
        for (int m = 0; m < MM; ++m)
            s = fmaf(hdn[n][m], w2p[(size_t)m * NN], s);
        att[k][n] = s;
    }
    __syncthreads();

    if (threadIdx.x < NN) {
        int k = threadIdx.x;
        float mx = -1e30f;
#pragma unroll
        for (int n = 0; n < NN; ++n) mx = fmaxf(mx, att[k][n]);
        float ex[NN];
        float sum = 0.f;
#pragma unroll
        for (int n = 0; n < NN; ++n) { ex[n] = expf(att[k][n] - mx); sum += ex[n]; }
        float inv = 1.f / sum;
#pragma unroll
        for (int n = 0; n < NN; ++n) g_att[h][k][n] = ex[n] * inv;
    }
}

// ---------------- Kernel D: h' = att @ f, conv over heads, relu, residual ----------------
// grid: (dch=4, k=17), block 128 (one d each)
__global__ void kD(const float* __restrict__ Xs, const float* __restrict__ ROIs,
                   const float* __restrict__ conv_w, const float* __restrict__ conv_b,
                   float* __restrict__ out, int out_size) {
    const int dch = blockIdx.x;
    const int k   = blockIdx.y;
    const int d   = dch * 128 + threadIdx.x;

    __shared__ float w_s[HH][NN];
    // FIX (R1): HH*NN = 136 > 128 threads -> must loop, not a single guarded write
    for (int idx = threadIdx.x; idx < HH * NN; idx += 128) {
        int h = idx / NN, n = idx % NN;
        w_s[h][n] = conv_w[h] * g_att[h][k][n];
    }
    __syncthreads();

    float acc = conv_b[0];
#pragma unroll
    for (int h = 0; h < HH; ++h)
#pragma unroll
        for (int n = 0; n < NN; ++n)
            acc = fmaf(w_s[h][n], g_f[h][n][d], acc);

    out[k * DD + d] = fmaxf(acc, 0.f) + Xs[k * DD + d];

    // ROIs passthrough (second output of the reference tuple), if room exists
    if (k == 0 && dch == 0 && threadIdx.x < NN * 3 && out_size >= NN * DD + NN * 3)
        out[NN * DD + threadIdx.x] = ROIs[threadIdx.x];
}

// ---------------- launch ----------------
extern "C" void kernel_launch(void* const* d_in, const int* in_sizes, int n_in,
                              void* d_out, int out_size) {
    // Resolve inputs by element count (all ten are distinct) — robust to ordering.
    const float *Xs = 0, *ROIs = 0, *FC = 0, *W1 = 0, *b1 = 0, *W2 = 0, *b2 = 0,
                *cw = 0, *cb = 0;
    for (int i = 0; i < n_in; ++i) {
        const float* p = (const float*)d_in[i];
        switch (in_sizes[i]) {
            case NN * DD:           Xs = p; break;   // 8704
            case NN * 3:            ROIs = p; break; // 51
            case NN * NN:           /* adj */ break; // 289
            case HH * DD * DD:      FC = p; break;   // 2097152
            case HH * CIN * MM:     W1 = p; break;   // 1054720
            case HH * MM:           b1 = p; break;   // 2048
            case HH * MM * NN:      W2 = p; break;   // 34816
            case HH * NN:           b2 = p; break;   // 136
            case HH:                cw = p; break;   // 8
            case 1:                 cb = p; break;   // 1
            default: break;
        }
    }
    float* out = (float*)d_out;

    kA<<<dim3(8, 4, HH), 128>>>(Xs, FC);
    kB<<<dim3(8, 2, HH), 128>>>(ROIs, W1);
    kC<<<HH, 320>>>(W2, b1, b2);
    kD<<<dim3(4, NN), 128>>>(Xs, ROIs, cw, cb, out, out_size);
}

// round 3
// speedup vs baseline: 1.5990x; 1.5990x over previous
#include <cuda_runtime.h>
#include <math.h>

#define NN 17      // nodes
#define DD 512     // feature dim
#define HH 8       // heads
#define MM 256     // MLP hidden
#define CIN 515    // D + 3

// ---------------- device scratch ----------------
__device__ float g_pA[16][HH][NN][DD];  // partials of Xs@FC over 16 d-chunks
__device__ float g_f[HH][NN][DD];       // f = relu(Xs@FC)
__device__ float g_pB[16][HH][NN][MM];  // partials of cat@W1 over 16 c-chunks
__device__ float g_att[HH][NN][NN];     // softmax(att) * conv_w[h], [h][k][n]

// ---------------- Kernel A: partial f = Xs @ FC ----------------
// grid (dc=16, h=8) = 128 blocks, 256 threads; thread owns e=2*tid (float2)
__global__ void kA(const float* __restrict__ Xs, const float* __restrict__ FC) {
    const int dc = blockIdx.x;
    const int h  = blockIdx.y;
    const int tid = threadIdx.x;
    const int e  = tid * 2;
    const int d0 = dc * 32;

    __shared__ float xs[NN][32];
    for (int idx = tid; idx < NN * 32; idx += 256)
        xs[idx >> 5][idx & 31] = Xs[(idx >> 5) * DD + d0 + (idx & 31)];
    __syncthreads();

    float2 acc[NN];
#pragma unroll
    for (int n = 0; n < NN; ++n) acc[n] = make_float2(0.f, 0.f);

    const float* base = FC + ((size_t)h * DD + d0) * DD + e;

    // 8-deep software pipeline over the 32 d-iterations
    float2 buf[8];
#pragma unroll
    for (int p = 0; p < 8; ++p)
        buf[p] = *(const float2*)(base + (size_t)p * DD);
#pragma unroll
    for (int dd = 0; dd < 32; ++dd) {
        float2 fc = buf[dd & 7];
        if (dd + 8 < 32)
            buf[dd & 7] = *(const float2*)(base + (size_t)(dd + 8) * DD);
#pragma unroll
        for (int n = 0; n < NN; ++n) {
            float x = xs[n][dd];
            acc[n].x = fmaf(x, fc.x, acc[n].x);
            acc[n].y = fmaf(x, fc.y, acc[n].y);
        }
    }
#pragma unroll
    for (int n = 0; n < NN; ++n)
        *(float2*)&g_pA[dc][h][n][e] = acc[n];
}

// ---------------- Kernel B: reduce f chunk + relu, partial cat @ W1 ----------------
// grid (cc=16, h=8) = 128 blocks, 128 threads; thread owns m=2*tid (float2)
__global__ void kB(const float* __restrict__ ROIs, const float* __restrict__ W1) {
    const int cc = blockIdx.x;
    const int h  = blockIdx.y;
    const int tid = threadIdx.x;
    const int m  = tid * 2;
    const int c0 = cc * 32;

    __shared__ float cat_s[NN][32];
    __shared__ float coord_s[NN][3];

    for (int idx = tid; idx < NN * 32; idx += 128) {
        int n = idx >> 5, cp = idx & 31;
        float v = 0.f;
#pragma unroll
        for (int dc = 0; dc < 16; ++dc) v += g_pA[dc][h][n][c0 + cp];
        v = fmaxf(v, 0.f);
        cat_s[n][cp] = v;
        g_f[h][n][c0 + cp] = v;
    }
    if (cc == 0) {
        for (int idx = tid; idx < NN * 3; idx += 128)
            coord_s[idx / 3][idx % 3] = ROIs[idx];
    }
    __syncthreads();

    float2 acc[NN];
#pragma unroll
    for (int n = 0; n < NN; ++n) acc[n] = make_float2(0.f, 0.f);

    const float* base = W1 + ((size_t)h * CIN + c0) * MM + m;
    float2 buf[8];
#pragma unroll
    for (int p = 0; p < 8; ++p)
        buf[p] = *(const float2*)(base + (size_t)p * MM);
#pragma unroll
    for (int cp = 0; cp < 32; ++cp) {
        float2 w = buf[cp & 7];
        if (cp + 8 < 32)
            buf[cp & 7] = *(const float2*)(base + (size_t)(cp + 8) * MM);
#pragma unroll
        for (int n = 0; n < NN; ++n) {
            float c = cat_s[n][cp];
            acc[n].x = fmaf(c, w.x, acc[n].x);
            acc[n].y = fmaf(c, w.y, acc[n].y);
        }
    }
    if (cc == 0) {
#pragma unroll
        for (int j = 0; j < 3; ++j) {
            float2 w = *(const float2*)&W1[((size_t)h * CIN + DD + j) * MM + m];
#pragma unroll
            for (int n = 0; n < NN; ++n) {
                float c = coord_s[n][j];
                acc[n].x = fmaf(c, w.x, acc[n].x);
                acc[n].y = fmaf(c, w.y, acc[n].y);
            }
        }
    }
#pragma unroll
    for (int n = 0; n < NN; ++n)
        *(float2*)&g_pB[cc][h][n][m] = acc[n];
}

// ---------------- Kernel C: tanh MLP out + W2 GEMM + softmax ----------------
// grid 8 (head), 256 threads
__global__ void kC(const float* __restrict__ W2, const float* __restrict__ b1,
                   const float* __restrict__ b2, const float* __restrict__ conv_w) {
    const int h = blockIdx.x;
    const int tid = threadIdx.x;

    __shared__ float hdn[NN][MM];           // tanh activations
    __shared__ float patt[8][NN][NN + 1];   // per-m-group partials [mq][n][k]
    __shared__ float att[NN][NN];           // logits [k][n]

    // phase 1: reduce 16 partials + bias + tanh (float2 per thread-iter)
    for (int idx = tid; idx < NN * 128; idx += 256) {
        int n = idx >> 7, mp = idx & 127;
        int m = mp * 2;
        float2 s = *(const float2*)&b1[h * MM + m];
#pragma unroll
        for (int cc = 0; cc < 16; ++cc) {
            float2 v = *(const float2*)&g_pB[cc][h][n][m];
            s.x += v.x; s.y += v.y;
        }
        hdn[n][m]     = tanhf(s.x);
        hdn[n][m + 1] = tanhf(s.y);
    }
    __syncthreads();

    // phase 2: att logits = hdn @ W2, split m across 8 warps, lane = k
    {
        const int mq = tid >> 5, lane = tid & 31;
        if (lane < NN) {
            float acc[NN];
#pragma unroll
            for (int n = 0; n < NN; ++n) acc[n] = 0.f;
            const float* w2p = W2 + ((size_t)h * MM + mq * 32) * NN + lane;
#pragma unroll 8
            for (int mm = 0; mm < 32; ++mm) {
                float w = w2p[(size_t)mm * NN];
                const int m = mq * 32 + mm;
#pragma unroll
                for (int n = 0; n < NN; ++n)
                    acc[n] = fmaf(hdn[n][m], w, acc[n]);
            }
#pragma unroll
            for (int n = 0; n < NN; ++n)
                patt[mq][n][lane] = acc[n];
        }
    }
    __syncthreads();

    // reduce m-groups + bias
    for (int idx = tid; idx < NN * NN; idx += 256) {
        int n = idx / NN, k = idx % NN;
        float s = b2[h * NN + k];
#pragma unroll
        for (int q = 0; q < 8; ++q) s += patt[q][n][k];
        att[k][n] = s;
    }
    __syncthreads();

    // phase 3: softmax over n, premultiply conv_w
    if (tid < NN) {
        const int k = tid;
        float mx = -1e30f;
#pragma unroll
        for (int n = 0; n < NN; ++n) mx = fmaxf(mx, att[k][n]);
        float ex[NN], sum = 0.f;
#pragma unroll
        for (int n = 0; n < NN; ++n) { ex[n] = expf(att[k][n] - mx); sum += ex[n]; }
        float scale = conv_w[h] / sum;
#pragma unroll
        for (int n = 0; n < NN; ++n) g_att[h][k][n] = ex[n] * scale;
    }
}

// ---------------- Kernel D: out = relu(sum_h,n attw*f + cb) + Xs ----------------
// grid (dch=4, k=17) = 68 blocks, 256 threads: tid = hgroup(2) x d(128)
__global__ void kD(const float* __restrict__ Xs, const float* __restrict__ ROIs,
                   const float* __restrict__ conv_b,
                   float* __restrict__ out, int out_size) {
    const int dch = blockIdx.x;
    const int k   = blockIdx.y;
    const int tid = threadIdx.x;
    const int hg  = tid >> 7;          // 0 or 1: heads 0-3 / 4-7
    const int dt  = tid & 127;
    const int d   = dch * 128 + dt;

    __shared__ float w[HH][NN];
    __shared__ float part[128];

    for (int idx = tid; idx < HH * NN; idx += 256)
        w[idx / NN][idx % NN] = g_att[idx / NN][k][idx % NN];
    __syncthreads();

    const int hb = hg * 4;
    float a0 = 0.f, a1 = 0.f;
#pragma unroll
    for (int hh = 0; hh < 4; ++hh) {
#pragma unroll
        for (int n = 0; n < NN; ++n) {
            float v = g_f[hb + hh][n][d];
            if (n & 1) a1 = fmaf(w[hb + hh][n], v, a1);
            else       a0 = fmaf(w[hb + hh][n], v, a0);
        }
    }
    float a = a0 + a1;
    if (hg == 1) part[dt] = a;
    __syncthreads();
    if (hg == 0) {
        float tot = a + part[dt] + conv_b[0];
        out[k * DD + d] = fmaxf(tot, 0.f) + Xs[k * DD + d];
    }

    if (k == 0 && dch == 0 && tid < NN * 3 && out_size >= NN * DD + NN * 3)
        out[NN * DD + tid] = ROIs[tid];
}

// ---------------- launch ----------------
extern "C" void kernel_launch(void* const* d_in, const int* in_sizes, int n_in,
                              void* d_out, int out_size) {
    const float *Xs = 0, *ROIs = 0, *FC = 0, *W1 = 0, *b1 = 0, *W2 = 0, *b2 = 0,
                *cw = 0, *cb = 0;
    for (int i = 0; i < n_in; ++i) {
        const float* p = (const float*)d_in[i];
        switch (in_sizes[i]) {
            case NN * DD:       Xs = p; break;
            case NN * 3:        ROIs = p; break;
            case NN * NN:       /* adj */ break;
            case HH * DD * DD:  FC = p; break;
            case HH * CIN * MM: W1 = p; break;
            case HH * MM:       b1 = p; break;
            case HH * MM * NN:  W2 = p; break;
            case HH * NN:       b2 = p; break;
            case HH:            cw = p; break;
            case 1:             cb = p; break;
            default: break;
        }
    }
    float* out = (float*)d_out;

    kA<<<dim3(16, 8), 256>>>(Xs, FC);
    kB<<<dim3(16, 8), 128>>>(ROIs, W1);
    kC<<<HH, 256>>>(W2, b1, b2, cw);
    kD<<<dim3(4, NN), 256>>>(Xs, ROIs, cb, out, out_size);
}

// round 4
// speedup vs baseline: 1.6105x; 1.0072x over previous
#include <cuda_runtime.h>
#include <math.h>

#define NN 17
#define DD 512
#define HH 8
#define MM 256
#define CIN 515

typedef unsigned long long u64;

// ---------------- f32x2 helpers ----------------
__device__ __forceinline__ void ffma2(u64& acc, u64 a, u64 b) {
    asm("fma.rn.f32x2 %0, %1, %2, %0;" : "+l"(acc) : "l"(a), "l"(b));
}
__device__ __forceinline__ u64 dup2(float x) {
    u64 r; asm("mov.b64 %0, {%1, %1};" : "=l"(r) : "f"(x)); return r;
}
__device__ __forceinline__ float2 unpack2(u64 a) {
    float2 f; asm("mov.b64 {%0, %1}, %2;" : "=f"(f.x), "=f"(f.y) : "l"(a)); return f;
}

// ---------------- device scratch ----------------
__device__ float g_pA[16][HH][NN][DD];   // partials of Xs@FC over 16 d-chunks (32 wide)
__device__ float g_f[HH][NN][DD];        // f = relu(Xs@FC)
__device__ float g_pB[32][HH][NN][MM];   // partials of cat@W1 over 32 c-chunks (16 wide)
__device__ float g_att[HH][NN][NN];      // softmax(att)*conv_w[h], [h][k][n]

// ---------------- Kernel A: partial f = Xs @ FC ----------------
// grid (dc=16, h=8) = 128 blocks x 256 thr; thread owns e = 2*tid (f32x2)
__global__ void __launch_bounds__(256) kA(const float* __restrict__ Xs,
                                          const float* __restrict__ FC) {
    const int dc = blockIdx.x, h = blockIdx.y, tid = threadIdx.x;
    const int d0 = dc * 32;

    // duplicated-pair broadcast operand: xs2[dd][n] = (x, x)
    __shared__ float2 xs2[32][18];
    for (int idx = tid; idx < NN * 32; idx += 256) {
        int n = idx >> 5, dd = idx & 31;
        float v = Xs[n * DD + d0 + dd];
        xs2[dd][n] = make_float2(v, v);
    }
    __syncthreads();

    u64 acc[18];
#pragma unroll
    for (int j = 0; j < 18; ++j) acc[j] = 0ull;

    // FC row stream: u64 = (FC[d][e], FC[d][e+1]); row stride 256 u64
    const u64* base = reinterpret_cast<const u64*>(FC + ((size_t)h * DD + d0) * DD) + tid;

    u64 buf[10];
#pragma unroll
    for (int p = 0; p < 10; ++p) buf[p] = base[(size_t)p * 256];

#pragma unroll
    for (int dd = 0; dd < 32; ++dd) {
        u64 fc = buf[dd % 10];
        if (dd + 10 < 32) buf[dd % 10] = base[(size_t)(dd + 10) * 256];
        const ulonglong2* row = reinterpret_cast<const ulonglong2*>(&xs2[dd][0]);
#pragma unroll
        for (int j = 0; j < 9; ++j) {
            ulonglong2 q = row[j];          // two dup-pairs: n=2j, n=2j+1
            ffma2(acc[2 * j],     q.x, fc);
            ffma2(acc[2 * j + 1], q.y, fc); // j==8,.y is pad (n=17), discarded
        }
    }
#pragma unroll
    for (int n = 0; n < NN; ++n)
        *reinterpret_cast<u64*>(&g_pA[dc][h][n][2 * tid]) = acc[n];
}

// ---------------- Kernel B: reduce f chunk + relu, partial cat @ W1 ----------------
// grid (cc=32, h=8) = 256 blocks x 128 thr; thread owns m = 2*tid
__global__ void __launch_bounds__(128) kB(const float* __restrict__ ROIs,
                                          const float* __restrict__ W1) {
    const int cc = blockIdx.x, h = blockIdx.y, tid = threadIdx.x;
    const int c0 = cc * 16;

    __shared__ float2 cat2[16][18];    // dup pairs [cp][n]
    __shared__ float2 coord2[3][18];   // dup pairs [j][n]

    for (int idx = tid; idx < NN * 16; idx += 128) {
        int n = idx >> 4, cp = idx & 15;
        float v = 0.f;
#pragma unroll
        for (int dc = 0; dc < 16; ++dc) v += g_pA[dc][h][n][c0 + cp];
        v = fmaxf(v, 0.f);
        g_f[h][n][c0 + cp] = v;
        cat2[cp][n] = make_float2(v, v);
    }
    if (cc == 0) {
        for (int idx = tid; idx < NN * 3; idx += 128) {
            int n = idx / 3, j = idx % 3;
            float v = ROIs[idx];
            coord2[j][n] = make_float2(v, v);
        }
    }
    __syncthreads();

    u64 acc[18];
#pragma unroll
    for (int j = 0; j < 18; ++j) acc[j] = 0ull;

    const u64* base = reinterpret_cast<const u64*>(W1 + ((size_t)h * CIN + c0) * MM) + tid;
    u64 buf[8];
#pragma unroll
    for (int p = 0; p < 8; ++p) buf[p] = base[(size_t)p * 128];

#pragma unroll
    for (int cp = 0; cp < 16; ++cp) {
        u64 w = buf[cp & 7];
        if (cp + 8 < 16) buf[cp & 7] = base[(size_t)(cp + 8) * 128];
        const ulonglong2* row = reinterpret_cast<const ulonglong2*>(&cat2[cp][0]);
#pragma unroll
        for (int j = 0; j < 9; ++j) {
            ulonglong2 q = row[j];
            ffma2(acc[2 * j],     q.x, w);
            ffma2(acc[2 * j + 1], q.y, w);
        }
    }
    if (cc == 0) {
#pragma unroll
        for (int j = 0; j < 3; ++j) {
            u64 w = *reinterpret_cast<const u64*>(W1 + ((size_t)h * CIN + DD + j) * MM + 2 * tid);
            const ulonglong2* row = reinterpret_cast<const ulonglong2*>(&coord2[j][0]);
#pragma unroll
            for (int q = 0; q < 9; ++q) {
                ulonglong2 c = row[q];
                ffma2(acc[2 * q],     c.x, w);
                ffma2(acc[2 * q + 1], c.y, w);
            }
        }
    }
#pragma unroll
    for (int n = 0; n < NN; ++n)
        *reinterpret_cast<u64*>(&g_pB[cc][h][n][2 * tid]) = acc[n];
}

// ---------------- Kernel C: tanh MLP + W2 GEMM + softmax ----------------
// grid 8 (head) x 512 thr
__global__ void __launch_bounds__(512) kC(const float* __restrict__ W2,
                                          const float* __restrict__ b1,
                                          const float* __restrict__ b2,
                                          const float* __restrict__ conv_w) {
    const int h = blockIdx.x, tid = threadIdx.x;

    __shared__ u64   hdnp[MM][10];       // row m: n-pairs (hdn[2j][m], hdn[2j+1][m]); 20.5 KB
    __shared__ float patt[16][NN][20];   // per-warp partial logits [mq][n][k]; 21.8 KB
    __shared__ float att[NN][NN];        // logits [k][n]

    // phase 1: reduce 32 partials (float4) + bias + tanh -> hdnp (transposed)
    float* hdnf = reinterpret_cast<float*>(hdnp);
    for (int idx = tid; idx < NN * 64; idx += 512) {
        int n = idx >> 6, m = (idx & 63) * 4;
        float4 s = *reinterpret_cast<const float4*>(b1 + h * MM + m);
#pragma unroll
        for (int cc = 0; cc < 32; ++cc) {
            float4 v = *reinterpret_cast<const float4*>(&g_pB[cc][h][n][m]);
            s.x += v.x; s.y += v.y; s.z += v.z; s.w += v.w;
        }
        hdnf[(m + 0) * 20 + n] = tanhf(s.x);
        hdnf[(m + 1) * 20 + n] = tanhf(s.y);
        hdnf[(m + 2) * 20 + n] = tanhf(s.z);
        hdnf[(m + 3) * 20 + n] = tanhf(s.w);
    }
    __syncthreads();

    // phase 2: logits = hdn @ W2; warp mq handles 16 m's, lane = k
    {
        const int mq = tid >> 5, lane = tid & 31;
        if (lane < NN) {
            u64 acc2[9];
#pragma unroll
            for (int j = 0; j < 9; ++j) acc2[j] = 0ull;
#pragma unroll
            for (int mm = 0; mm < 16; ++mm) {
                const int m = mq * 16 + mm;
                u64 w2 = dup2(W2[((size_t)h * MM + m) * NN + lane]);
                const ulonglong2* row = reinterpret_cast<const ulonglong2*>(&hdnp[m][0]);
#pragma unroll
                for (int j = 0; j < 4; ++j) {
                    ulonglong2 q = row[j];
                    ffma2(acc2[2 * j],     q.x, w2);
                    ffma2(acc2[2 * j + 1], q.y, w2);
                }
                ffma2(acc2[8], hdnp[m][8], w2);
            }
#pragma unroll
            for (int j = 0; j < 9; ++j) {
                float2 v = unpack2(acc2[j]);
                patt[mq][2 * j][lane] = v.x;
                if (2 * j + 1 < NN) patt[mq][2 * j + 1][lane] = v.y;
            }
        }
    }
    __syncthreads();

    // reduce warp partials + bias
    for (int idx = tid; idx < NN * NN; idx += 512) {
        int n = idx / NN, k = idx % NN;
        float s = b2[h * NN + k];
#pragma unroll
        for (int q = 0; q < 16; ++q) s += patt[q][n][k];
        att[k][n] = s;
    }
    __syncthreads();

    // phase 3: softmax over n, premultiply conv_w
    if (tid < NN) {
        const int k = tid;
        float mx = -1e30f;
#pragma unroll
        for (int n = 0; n < NN; ++n) mx = fmaxf(mx, att[k][n]);
        float ex[NN], sum = 0.f;
#pragma unroll
        for (int n = 0; n < NN; ++n) { ex[n] = expf(att[k][n] - mx); sum += ex[n]; }
        float scale = conv_w[h] / sum;
#pragma unroll
        for (int n = 0; n < NN; ++n) g_att[h][k][n] = ex[n] * scale;
    }
}

// ---------------- Kernel D: out = relu(sum_{h,n} w*f + cb) + Xs ----------------
// grid (dch=2, k=17) = 34 blocks x 128 thr; thread owns d = dch*256 + 2*tid
__global__ void __launch_bounds__(128) kD(const float* __restrict__ Xs,
                                          const float* __restrict__ ROIs,
                                          const float* __restrict__ conv_b,
                                          float* __restrict__ out, int out_size) {
    const int dch = blockIdx.x, k = blockIdx.y, tid = threadIdx.x;
    const int d = dch * 256 + 2 * tid;

    __shared__ u64 w2s[HH * NN];   // dup pairs of conv_w[h]*att[h][k][n]
    for (int idx = tid; idx < HH * NN; idx += 128) {
        int h = idx / NN, n = idx % NN;
        w2s[idx] = dup2(g_att[h][k][n]);
    }
    __syncthreads();

    // f flat: [(h*17+n)][512]; u64 stride per i = 256
    const u64* fbase = reinterpret_cast<const u64*>(g_f) + dch * 128 + tid;

    u64 acc[4];
#pragma unroll
    for (int j = 0; j < 4; ++j) acc[j] = 0ull;

    u64 buf[16];
#pragma unroll
    for (int p = 0; p < 16; ++p) buf[p] = fbase[(size_t)p * 256];

#pragma unroll
    for (int i = 0; i < HH * NN; ++i) {
        u64 f2 = buf[i & 15];
        if (i + 16 < HH * NN) buf[i & 15] = fbase[(size_t)(i + 16) * 256];
        ffma2(acc[i & 3], w2s[i], f2);
    }

    float2 a0 = unpack2(acc[0]), a1 = unpack2(acc[1]);
    float2 a2 = unpack2(acc[2]), a3 = unpack2(acc[3]);
    float cb = conv_b[0];
    float rx = a0.x + a1.x + a2.x + a3.x + cb;
    float ry = a0.y + a1.y + a2.y + a3.y + cb;
    const float2 xv = *reinterpret_cast<const float2*>(Xs + k * DD + d);
    float2 r = make_float2(fmaxf(rx, 0.f) + xv.x, fmaxf(ry, 0.f) + xv.y);
    *reinterpret_cast<float2*>(out + k * DD + d) = r;

    if (k == 0 && dch == 0 && tid < NN * 3 && out_size >= NN * DD + NN * 3)
        out[NN * DD + tid] = ROIs[tid];
}

// ---------------- launch ----------------
extern "C" void kernel_launch(void* const* d_in, const int* in_sizes, int n_in,
                              void* d_out, int out_size) {
    const float *Xs = 0, *ROIs = 0, *FC = 0, *W1 = 0, *b1 = 0, *W2 = 0, *b2 = 0,
                *cw = 0, *cb = 0;
    for (int i = 0; i < n_in; ++i) {
        const float* p = (const float*)d_in[i];
        switch (in_sizes[i]) {
            case NN * DD:       Xs = p; break;
            case NN * 3:        ROIs = p; break;
            case NN * NN:       /* adj */ break;
            case HH * DD * DD:  FC = p; break;
            case HH * CIN * MM: W1 = p; break;
            case HH * MM:       b1 = p; break;
            case HH * MM * NN:  W2 = p; break;
            case HH * NN:       b2 = p; break;
            case HH:            cw = p; break;
            case 1:             cb = p; break;
            default: break;
        }
    }
    float* out = (float*)d_out;

    kA<<<dim3(16, 8), 256>>>(Xs, FC);
    kB<<<dim3(32, 8), 128>>>(ROIs, W1);
    kC<<<8, 512>>>(W2, b1, b2, cw);
    kD<<<dim3(2, NN), 128>>>(Xs, ROIs, cb, out, out_size);
}